// round 1
// baseline (speedup 1.0000x reference)
#include <cuda_runtime.h>
#include <cuda_bf16.h>

// Problem constants (fixed by the reference): B=2048, T=512, I=4, H=64, O=4
#define TT 512
#define BB 2048
#define II 4
#define HH 64
#define GG 256   // 4*H gates
#define OO 4
#define NB 8     // batch rows per block

// Packed fp32x2 FMA (Blackwell FFMA2) — 2 FMA per issue, only reachable via PTX.
__device__ __forceinline__ void fma2(unsigned long long &a, unsigned long long w, unsigned long long h){
    asm("fma.rn.f32x2 %0, %1, %2, %0;" : "+l"(a) : "l"(w), "l"(h));
}
__device__ __forceinline__ float2 unpack2(unsigned long long v){
    float2 r; asm("mov.b64 {%0, %1}, %2;" : "=f"(r.x), "=f"(r.y) : "l"(v)); return r;
}
// Fast, NaN-safe activations (MUFU ex2 + rcp; rel err ~1e-7)
__device__ __forceinline__ float sigf(float xv){
    return __fdividef(1.f, 1.f + __expf(-xv));
}
__device__ __forceinline__ float tanhfast(float xv){
    // tanh(x) = 2*sigmoid(2x) - 1 ; safe at both extremes (exp->inf gives rcp->0)
    return __fmaf_rn(2.f, sigf(2.f * xv), -1.f);
}

__global__ void __launch_bounds__(256, 2) lstm_fused_kernel(
    const float* __restrict__ x,     // [B, T, I]
    const float* __restrict__ W_ih,  // [4H, I]
    const float* __restrict__ W_hh,  // [4H, H]
    const float* __restrict__ b_ih,  // [4H]
    const float* __restrict__ b_hh,  // [4H]
    const float* __restrict__ W_fc,  // [O, H]
    const float* __restrict__ b_fc,  // [O]
    float* __restrict__ out)         // [1, B, O]
{
    __shared__ __align__(16) float h_sh[NB][HH];    // current hidden state
    __shared__ float g_sh[NB][GG];                  // pre-activation gates
    __shared__ float4 x_sh[2][NB];                  // double-buffered x_t (I=4 -> float4)

    const int tid   = threadIdx.x;                  // == gate id g in [0,256)
    const int bbase = blockIdx.x * NB;

    // --- Load this gate's W_hh row into registers as 32 packed fp32 pairs ---
    unsigned long long w[32];
    {
        const unsigned long long* wp =
            (const unsigned long long*)(W_hh + (size_t)tid * HH);   // 256B-aligned row
        #pragma unroll
        for (int j = 0; j < 32; j++) w[j] = wp[j];
    }
    const float wih0 = W_ih[tid*4 + 0];
    const float wih1 = W_ih[tid*4 + 1];
    const float wih2 = W_ih[tid*4 + 2];
    const float wih3 = W_ih[tid*4 + 3];
    const float bias = b_ih[tid] + b_hh[tid];

    // --- Cell-update mapping: thread handles 2 (b, h_idx) items; c lives in regs ---
    const int b0u = tid >> 6;        // items 0..255   -> b 0..3
    const int h0u = tid & 63;
    const int b1u = 4 + b0u;         // items 256..511 -> b 4..7
    const int h1u = h0u;
    float c0 = 0.f, c1 = 0.f;

    // init h = 0, preload x for t=0
    for (int i = tid; i < NB * HH; i += 256) ((float*)h_sh)[i] = 0.f;
    if (tid < NB)
        x_sh[0][tid] = ((const float4*)x)[ (size_t)(bbase + tid) * TT ];
    __syncthreads();

    for (int t = 0; t < TT; t++){
        // Prefetch next step's x (latency hidden under the gate GEMV below)
        float4 xnext;
        const bool pre = (tid < NB) && (t + 1 < TT);
        if (pre) xnext = ((const float4*)x)[ (size_t)(bbase + tid) * TT + (t + 1) ];

        const float4* xcur = x_sh[t & 1];

        // --- Gate GEMV: gate[b][tid] = bias + W_ih[tid,:]·x_t[b] + W_hh[tid,:]·h[b] ---
        #pragma unroll
        for (int b = 0; b < NB; b++){
            const ulonglong2* hp = (const ulonglong2*)h_sh[b];   // broadcast LDS.128
            unsigned long long a0 = 0ull, a1 = 0ull, a2 = 0ull, a3 = 0ull;
            #pragma unroll
            for (int j = 0; j < 8; j++){
                ulonglong2 hv0 = hp[2*j];
                ulonglong2 hv1 = hp[2*j + 1];
                fma2(a0, w[4*j + 0], hv0.x);
                fma2(a1, w[4*j + 1], hv0.y);
                fma2(a2, w[4*j + 2], hv1.x);
                fma2(a3, w[4*j + 3], hv1.y);
            }
            float2 f0 = unpack2(a0), f1 = unpack2(a1), f2 = unpack2(a2), f3 = unpack2(a3);
            float s = ((f0.x + f0.y) + (f1.x + f1.y)) + ((f2.x + f2.y) + (f3.x + f3.y));
            float4 xv = xcur[b];
            s += bias;
            s = __fmaf_rn(wih0, xv.x, s);
            s = __fmaf_rn(wih1, xv.y, s);
            s = __fmaf_rn(wih2, xv.z, s);
            s = __fmaf_rn(wih3, xv.w, s);
            g_sh[b][tid] = s;
        }
        if (pre) x_sh[(t + 1) & 1][tid] = xnext;
        __syncthreads();

        // --- Elementwise LSTM cell update (PyTorch gate order i,f,g,o) ---
        {
            float gi = g_sh[b0u][h0u];
            float gf = g_sh[b0u][HH   + h0u];
            float gg = g_sh[b0u][2*HH + h0u];
            float go = g_sh[b0u][3*HH + h0u];
            c0 = sigf(gf) * c0 + sigf(gi) * tanhfast(gg);
            h_sh[b0u][h0u] = sigf(go) * tanhfast(c0);

            float gi1 = g_sh[b1u][h1u];
            float gf1 = g_sh[b1u][HH   + h1u];
            float gg1 = g_sh[b1u][2*HH + h1u];
            float go1 = g_sh[b1u][3*HH + h1u];
            c1 = sigf(gf1) * c1 + sigf(gi1) * tanhfast(gg1);
            h_sh[b1u][h1u] = sigf(go1) * tanhfast(c1);
        }
        __syncthreads();
    }

    // --- FC head: out[b][o] = b_fc[o] + W_fc[o,:]·h[b] ---
    if (tid < NB * OO){
        const int b = tid >> 2, o = tid & 3;
        float s = b_fc[o];
        #pragma unroll
        for (int k = 0; k < HH; k++)
            s = __fmaf_rn(W_fc[o*HH + k], h_sh[b][k], s);
        out[(size_t)(bbase + b) * OO + o] = s;
    }
}

extern "C" void kernel_launch(void* const* d_in, const int* in_sizes, int n_in,
                              void* d_out, int out_size)
{
    const float* x    = (const float*)d_in[0];
    const float* W_ih = (const float*)d_in[1];
    const float* W_hh = (const float*)d_in[2];
    const float* b_ih = (const float*)d_in[3];
    const float* b_hh = (const float*)d_in[4];
    const float* W_fc = (const float*)d_in[5];
    const float* b_fc = (const float*)d_in[6];
    float* out = (float*)d_out;

    lstm_fused_kernel<<<BB / NB, 256>>>(x, W_ih, W_hh, b_ih, b_hh, W_fc, b_fc, out);
}

// round 2
// speedup vs baseline: 1.1904x; 1.1904x over previous
#include <cuda_runtime.h>
#include <cuda_bf16.h>

// Problem constants: B=2048, T=512, I=4, H=64, O=4
#define TT 512
#define BB 2048
#define HH 64
#define GG 256   // 4*H gates
#define OO 4
#define NB 7     // batch rows per block  -> grid 296 = 2 blocks on every one of 148 SMs
#define GRID 296

// ---- packed fp32x2 ops (Blackwell) ----
__device__ __forceinline__ void fma2(unsigned long long &a, unsigned long long w, unsigned long long h){
    asm("fma.rn.f32x2 %0, %1, %2, %0;" : "+l"(a) : "l"(w), "l"(h));
}
__device__ __forceinline__ unsigned long long add2(unsigned long long a, unsigned long long b){
    unsigned long long r; asm("add.rn.f32x2 %0, %1, %2;" : "=l"(r) : "l"(a), "l"(b)); return r;
}
__device__ __forceinline__ float2 unpack2(unsigned long long v){
    float2 r; asm("mov.b64 {%0, %1}, %2;" : "=f"(r.x), "=f"(r.y) : "l"(v)); return r;
}
__device__ __forceinline__ unsigned long long pack2(float lo, float hi){
    unsigned long long r; asm("mov.b64 %0, {%1, %2};" : "=l"(r) : "f"(lo), "f"(hi)); return r;
}
// ---- native MUFU tanh (1 op) + sigmoid via tanh ----
__device__ __forceinline__ float tanh_ap(float x){
    float r; asm("tanh.approx.f32 %0, %1;" : "=f"(r) : "f"(x)); return r;
}
__device__ __forceinline__ float sig_ap(float x){
    return __fmaf_rn(0.5f, tanh_ap(0.5f * x), 0.5f);
}

__global__ void __launch_bounds__(256, 2) lstm_fused_kernel(
    const float* __restrict__ x,     // [B, T, I]
    const float* __restrict__ W_ih,  // [4H, I]
    const float* __restrict__ W_hh,  // [4H, H]
    const float* __restrict__ b_ih,  // [4H]
    const float* __restrict__ b_hh,  // [4H]
    const float* __restrict__ W_fc,  // [O, H]
    const float* __restrict__ b_fc,  // [O]
    float* __restrict__ out)         // [1, B, O]
{
    __shared__ __align__(16) float h_sh[NB][HH];     // hidden state
    __shared__ __align__(16) float g_sh[NB][GG];     // pre-activation gates
    __shared__ __align__(16) float4 x_sh[2][NB];     // double-buffered x_t

    const int tid   = threadIdx.x;                   // gate id g in [0,256)
    const int bbase = blockIdx.x * NB;

    // W_hh row for this gate as 32 packed fp32 pairs (64 regs)
    unsigned long long w[32];
    {
        const unsigned long long* wp = (const unsigned long long*)(W_hh + (size_t)tid * HH);
        #pragma unroll
        for (int j = 0; j < 32; j++) w[j] = wp[j];
    }
    const unsigned long long wih01 = pack2(W_ih[tid*4 + 0], W_ih[tid*4 + 1]);
    const unsigned long long wih23 = pack2(W_ih[tid*4 + 2], W_ih[tid*4 + 3]);
    const unsigned long long bias2 = pack2(b_ih[tid] + b_hh[tid], 0.f);

    // cell-update mapping: item1 = tid (b 0..3), item2 = 256+tid for tid<192 (b 4..6)
    const int b0u = tid >> 6;
    const int h0u = tid & 63;
    const int b1u = 4 + b0u;
    const bool has2 = (tid < (NB - 4) * HH);         // tid < 192
    float c0 = 0.f, c1 = 0.f;

    for (int i = tid; i < NB * HH; i += 256) ((float*)h_sh)[i] = 0.f;
    if (tid < NB && (bbase + tid) < BB)
        x_sh[0][tid] = ((const float4*)x)[ (size_t)(bbase + tid) * TT ];
    __syncthreads();

    for (int t = 0; t < TT; t++){
        // prefetch next x (hidden under GEMV)
        float4 xnext;
        const bool pre = (tid < NB) && (t + 1 < TT) && ((bbase + tid) < BB);
        if (pre) xnext = ((const float4*)x)[ (size_t)(bbase + tid) * TT + (t + 1) ];

        const ulonglong2* xcur = (const ulonglong2*)x_sh[t & 1];

        // ---- gate GEMV: g_sh[b][tid] = bias + W_ih·x_t[b] + W_hh·h[b] ----
        #pragma unroll
        for (int b = 0; b < NB; b++){
            const ulonglong2* hp = (const ulonglong2*)h_sh[b];   // broadcast LDS.128
            ulonglong2 xv = xcur[b];
            unsigned long long a0 = bias2, a1 = 0ull, a2 = 0ull, a3 = 0ull;
            fma2(a0, wih01, xv.x);
            fma2(a1, wih23, xv.y);
            #pragma unroll
            for (int j = 0; j < 8; j++){
                ulonglong2 hv0 = hp[2*j];
                ulonglong2 hv1 = hp[2*j + 1];
                fma2(a0, w[4*j + 0], hv0.x);
                fma2(a1, w[4*j + 1], hv0.y);
                fma2(a2, w[4*j + 2], hv1.x);
                fma2(a3, w[4*j + 3], hv1.y);
            }
            unsigned long long s2 = add2(add2(a0, a1), add2(a2, a3));
            float2 f = unpack2(s2);
            g_sh[b][tid] = f.x + f.y;
        }
        if (pre) x_sh[(t + 1) & 1][tid] = xnext;
        __syncthreads();

        // ---- LSTM cell update (gate order i,f,g,o), tanh.approx activations ----
        {
            float gi = g_sh[b0u][h0u];
            float gf = g_sh[b0u][HH   + h0u];
            float gg = g_sh[b0u][2*HH + h0u];
            float go = g_sh[b0u][3*HH + h0u];
            float gi1, gf1, gg1, go1;
            if (has2){
                gi1 = g_sh[b1u][h0u];
                gf1 = g_sh[b1u][HH   + h0u];
                gg1 = g_sh[b1u][2*HH + h0u];
                go1 = g_sh[b1u][3*HH + h0u];
            }
            c0 = sig_ap(gf) * c0 + sig_ap(gi) * tanh_ap(gg);
            h_sh[b0u][h0u] = sig_ap(go) * tanh_ap(c0);
            if (has2){
                c1 = sig_ap(gf1) * c1 + sig_ap(gi1) * tanh_ap(gg1);
                h_sh[b1u][h0u] = sig_ap(go1) * tanh_ap(c1);
            }
        }
        __syncthreads();
    }

    // ---- FC head ----
    if (tid < NB * OO){
        const int b = tid >> 2, o = tid & 3;
        if ((bbase + b) < BB){
            float s = b_fc[o];
            #pragma unroll
            for (int k = 0; k < HH; k++)
                s = __fmaf_rn(W_fc[o*HH + k], h_sh[b][k], s);
            out[(size_t)(bbase + b) * OO + o] = s;
        }
    }
}

extern "C" void kernel_launch(void* const* d_in, const int* in_sizes, int n_in,
                              void* d_out, int out_size)
{
    const float* x    = (const float*)d_in[0];
    const float* W_ih = (const float*)d_in[1];
    const float* W_hh = (const float*)d_in[2];
    const float* b_ih = (const float*)d_in[3];
    const float* b_hh = (const float*)d_in[4];
    const float* W_fc = (const float*)d_in[5];
    const float* b_fc = (const float*)d_in[6];
    float* out = (float*)d_out;

    lstm_fused_kernel<<<GRID, 256>>>(x, W_ih, W_hh, b_ih, b_hh, W_fc, b_fc, out);
}

// round 3
// speedup vs baseline: 1.4338x; 1.2044x over previous
#include <cuda_runtime.h>
#include <cuda_bf16.h>

// Problem constants: B=2048, T=512, I=4, H=64, O=4
#define TT 512
#define BB 2048
#define HH 64
#define GG 256   // 4*H gates
#define OO 4
#define NB 7     // batch rows per block
#define GRID 296 // 2 blocks per SM on 148 SMs
#define NT 128   // threads per block = gate pairs

// ---- packed fp32x2 ops (Blackwell) ----
__device__ __forceinline__ void fma2(unsigned long long &a, unsigned long long w, unsigned long long h){
    asm("fma.rn.f32x2 %0, %1, %2, %0;" : "+l"(a) : "l"(w), "l"(h));
}
__device__ __forceinline__ unsigned long long add2(unsigned long long a, unsigned long long b){
    unsigned long long r; asm("add.rn.f32x2 %0, %1, %2;" : "=l"(r) : "l"(a), "l"(b)); return r;
}
__device__ __forceinline__ float2 unpack2(unsigned long long v){
    float2 r; asm("mov.b64 {%0, %1}, %2;" : "=f"(r.x), "=f"(r.y) : "l"(v)); return r;
}
__device__ __forceinline__ unsigned long long pack2(float lo, float hi){
    unsigned long long r; asm("mov.b64 %0, {%1, %2};" : "=l"(r) : "f"(lo), "f"(hi)); return r;
}
// ---- native MUFU tanh + sigmoid via tanh ----
__device__ __forceinline__ float tanh_ap(float x){
    float r; asm("tanh.approx.f32 %0, %1;" : "=f"(r) : "f"(x)); return r;
}
__device__ __forceinline__ float sig_ap(float x){
    return __fmaf_rn(0.5f, tanh_ap(0.5f * x), 0.5f);
}

__global__ void __launch_bounds__(NT, 2) lstm_fused_kernel(
    const float* __restrict__ x,     // [B, T, I]
    const float* __restrict__ W_ih,  // [4H, I]
    const float* __restrict__ W_hh,  // [4H, H]
    const float* __restrict__ b_ih,  // [4H]
    const float* __restrict__ b_hh,  // [4H]
    const float* __restrict__ W_fc,  // [O, H]
    const float* __restrict__ b_fc,  // [O]
    float* __restrict__ out)         // [1, B, O]
{
    __shared__ __align__(16) float h_sh[NB][HH];     // hidden state
    __shared__ __align__(16) float g_sh[NB][GG];     // pre-activation gates
    __shared__ __align__(16) float4 x_sh[2][NB];     // double-buffered x_t

    const int tid   = threadIdx.x;                   // gate pair id p in [0,128)
    const int g0    = tid;                           // first gate row
    const int g1    = tid + 128;                     // second gate row
    const int bbase = blockIdx.x * NB;

    // Two W_hh rows in registers: 2 x 32 packed fp32 pairs (128 regs)
    unsigned long long wA[32], wB[32];
    {
        const unsigned long long* wpA = (const unsigned long long*)(W_hh + (size_t)g0 * HH);
        const unsigned long long* wpB = (const unsigned long long*)(W_hh + (size_t)g1 * HH);
        #pragma unroll
        for (int j = 0; j < 32; j++){ wA[j] = wpA[j]; wB[j] = wpB[j]; }
    }
    const unsigned long long wihA01 = pack2(W_ih[g0*4 + 0], W_ih[g0*4 + 1]);
    const unsigned long long wihA23 = pack2(W_ih[g0*4 + 2], W_ih[g0*4 + 3]);
    const unsigned long long wihB01 = pack2(W_ih[g1*4 + 0], W_ih[g1*4 + 1]);
    const unsigned long long wihB23 = pack2(W_ih[g1*4 + 2], W_ih[g1*4 + 3]);
    const unsigned long long biasA  = pack2(b_ih[g0] + b_hh[g0], 0.f);
    const unsigned long long biasB  = pack2(b_ih[g1] + b_hh[g1], 0.f);

    // Cell-update mapping: items i = tid + 128*j, j=0..3; 448 items total (j=3 only tid<64)
    float c0 = 0.f, c1 = 0.f, c2 = 0.f, c3 = 0.f;

    // init h = 0; zero x_sh (OOB rows read zeros); preload x for t=0
    for (int i = tid; i < NB * HH; i += NT) ((float*)h_sh)[i] = 0.f;
    if (tid < 2 * NB) ((float4*)x_sh)[tid] = make_float4(0.f, 0.f, 0.f, 0.f);
    __syncthreads();
    if (tid < NB && (bbase + tid) < BB)
        x_sh[0][tid] = ((const float4*)x)[ (size_t)(bbase + tid) * TT ];
    __syncthreads();

    for (int t = 0; t < TT; t++){
        // prefetch next x (latency hidden under GEMV)
        float4 xnext;
        const bool pre = (tid < NB) && (t + 1 < TT) && ((bbase + tid) < BB);
        if (pre) xnext = ((const float4*)x)[ (size_t)(bbase + tid) * TT + (t + 1) ];

        const ulonglong2* xcur = (const ulonglong2*)x_sh[t & 1];

        // ---- gate GEMV: both gate rows share each h load ----
        #pragma unroll
        for (int b = 0; b < NB; b++){
            const ulonglong2* hp = (const ulonglong2*)h_sh[b];   // broadcast LDS.128
            ulonglong2 xv = xcur[b];
            unsigned long long aA0 = biasA, aA1 = 0ull, aA2 = 0ull, aA3 = 0ull;
            unsigned long long aB0 = biasB, aB1 = 0ull, aB2 = 0ull, aB3 = 0ull;
            fma2(aA0, wihA01, xv.x);  fma2(aA1, wihA23, xv.y);
            fma2(aB0, wihB01, xv.x);  fma2(aB1, wihB23, xv.y);
            #pragma unroll
            for (int j = 0; j < 8; j++){
                ulonglong2 hv0 = hp[2*j];
                ulonglong2 hv1 = hp[2*j + 1];
                fma2(aA0, wA[4*j + 0], hv0.x);
                fma2(aA1, wA[4*j + 1], hv0.y);
                fma2(aA2, wA[4*j + 2], hv1.x);
                fma2(aA3, wA[4*j + 3], hv1.y);
                fma2(aB0, wB[4*j + 0], hv0.x);
                fma2(aB1, wB[4*j + 1], hv0.y);
                fma2(aB2, wB[4*j + 2], hv1.x);
                fma2(aB3, wB[4*j + 3], hv1.y);
            }
            unsigned long long sA = add2(add2(aA0, aA1), add2(aA2, aA3));
            unsigned long long sB = add2(add2(aB0, aB1), add2(aB2, aB3));
            float2 fA = unpack2(sA), fB = unpack2(sB);
            g_sh[b][g0] = fA.x + fA.y;
            g_sh[b][g1] = fB.x + fB.y;
        }
        if (pre) x_sh[(t + 1) & 1][tid] = xnext;
        __syncthreads();

        // ---- LSTM cell update: 448 items over 128 threads (3.5 each) ----
        {
            int i0 = tid;                 // j=0
            int i1 = tid + 128;           // j=1
            int i2 = tid + 256;           // j=2
            int i3 = tid + 384;           // j=3, only tid<64
            {
                int b = i0 >> 6, h = i0 & 63;
                float gi = g_sh[b][h], gf = g_sh[b][HH+h], gg = g_sh[b][2*HH+h], go = g_sh[b][3*HH+h];
                c0 = sig_ap(gf) * c0 + sig_ap(gi) * tanh_ap(gg);
                h_sh[b][h] = sig_ap(go) * tanh_ap(c0);
            }
            {
                int b = i1 >> 6, h = i1 & 63;
                float gi = g_sh[b][h], gf = g_sh[b][HH+h], gg = g_sh[b][2*HH+h], go = g_sh[b][3*HH+h];
                c1 = sig_ap(gf) * c1 + sig_ap(gi) * tanh_ap(gg);
                h_sh[b][h] = sig_ap(go) * tanh_ap(c1);
            }
            {
                int b = i2 >> 6, h = i2 & 63;
                float gi = g_sh[b][h], gf = g_sh[b][HH+h], gg = g_sh[b][2*HH+h], go = g_sh[b][3*HH+h];
                c2 = sig_ap(gf) * c2 + sig_ap(gi) * tanh_ap(gg);
                h_sh[b][h] = sig_ap(go) * tanh_ap(c2);
            }
            if (tid < 64){
                int b = i3 >> 6, h = i3 & 63;
                float gi = g_sh[b][h], gf = g_sh[b][HH+h], gg = g_sh[b][2*HH+h], go = g_sh[b][3*HH+h];
                c3 = sig_ap(gf) * c3 + sig_ap(gi) * tanh_ap(gg);
                h_sh[b][h] = sig_ap(go) * tanh_ap(c3);
            }
        }
        __syncthreads();
    }

    // ---- FC head: 28 outputs ----
    if (tid < NB * OO){
        const int b = tid >> 2, o = tid & 3;
        if ((bbase + b) < BB){
            float s = b_fc[o];
            #pragma unroll
            for (int k = 0; k < HH; k++)
                s = __fmaf_rn(W_fc[o*HH + k], h_sh[b][k], s);
            out[(size_t)(bbase + b) * OO + o] = s;
        }
    }
}

extern "C" void kernel_launch(void* const* d_in, const int* in_sizes, int n_in,
                              void* d_out, int out_size)
{
    const float* x    = (const float*)d_in[0];
    const float* W_ih = (const float*)d_in[1];
    const float* W_hh = (const float*)d_in[2];
    const float* b_ih = (const float*)d_in[3];
    const float* b_hh = (const float*)d_in[4];
    const float* W_fc = (const float*)d_in[5];
    const float* b_fc = (const float*)d_in[6];
    float* out = (float*)d_out;

    lstm_fused_kernel<<<GRID, NT>>>(x, W_ih, W_hh, b_ih, b_hh, W_fc, b_fc, out);
}